// round 5
// baseline (speedup 1.0000x reference)
#include <cuda_runtime.h>
#include <cstdint>

#define NN   5000
#define EE   80000
#define FEAT 47
#define FPAD 48

using ull = unsigned long long;

// ---------------- device scratch ----------------
__device__ int    g_count [NN];
__device__ int    g_rowptr[NN + 1];
__device__ int    g_cursor[NN];
__device__ int    g_pos   [EE];
__device__ int    g_srcp  [EE];          // CSR-ordered src node
__device__ float2 g_cp    [EE];          // CSR-ordered (c0, c1)
__device__ float  g_featp [NN * FPAD];

__device__ __forceinline__ float ftanh(float x) {
    float r; asm("tanh.approx.f32 %0, %1;" : "=f"(r) : "f"(x)); return r;
}
__device__ __forceinline__ float fsigmoid(float x) {     // 1 MUFU
    return fmaf(0.5f, ftanh(0.5f * x), 0.5f);
}
__device__ __forceinline__ ull pk(float lo, float hi) {
    ull r; asm("mov.b64 %0, {%1, %2};" : "=l"(r) : "f"(lo), "f"(hi)); return r;
}
__device__ __forceinline__ void upk(float& lo, float& hi, ull v) {
    asm("mov.b64 {%0, %1}, %2;" : "=f"(lo), "=f"(hi) : "l"(v));
}
__device__ __forceinline__ void ffma2(ull& acc, ull a, ull b) {
    asm("fma.rn.f32x2 %0, %1, %2, %0;" : "+l"(acc) : "l"(a), "l"(b));
}
__device__ __forceinline__ void lds2(ull& a, ull& b, uint32_t addr) {
    asm volatile("ld.shared.v2.b64 {%0, %1}, [%2];" : "=l"(a), "=l"(b) : "r"(addr));
}
__device__ __forceinline__ void lds1(ull& a, uint32_t addr) {
    asm volatile("ld.shared.b64 %0, [%1];" : "=l"(a) : "r"(addr));
}
__device__ __forceinline__ void cpasync16(uint32_t dst, const void* src) {
    asm volatile("cp.async.cg.shared.global [%0], [%1], 16;" :: "r"(dst), "l"(src));
}
#define CP_COMMIT() asm volatile("cp.async.commit_group;" ::: "memory")
#define CP_WAIT0()  asm volatile("cp.async.wait_group 0;"  ::: "memory")

// ---------------- zero counters + pad features ----------------
__global__ void k_prep(const float* __restrict__ feature) {
    int i = blockIdx.x * blockDim.x + threadIdx.x;
    if (i < NN) g_count[i] = 0;
    if (i < NN * FPAD) {
        int n = i / FPAD, c = i % FPAD;
        g_featp[i] = (c < FEAT) ? feature[n * FEAT + c] : 0.0f;
    }
}

// ---------------- count edges per dst ----------------
__global__ void k_count(const int* __restrict__ dst) {
    int e = blockIdx.x * blockDim.x + threadIdx.x;
    if (e < EE) atomicAdd(&g_count[dst[e]], 1);
}

// ---------------- exclusive scan (shfl-based, 1 block) ----------------
__global__ void k_scan() {
    __shared__ int wtot[32];
    int tid = threadIdx.x, lane = tid & 31, wid = tid >> 5;
    int base = tid * 5;
    int loc[5];
    int run = 0;
#pragma unroll
    for (int t = 0; t < 5; ++t) {
        loc[t] = run;
        int idx = base + t;
        run += (idx < NN) ? g_count[idx] : 0;
    }
    int own = run;
    int inc = run;
#pragma unroll
    for (int off = 1; off < 32; off <<= 1) {
        int v = __shfl_up_sync(0xffffffffu, inc, off);
        if (lane >= off) inc += v;
    }
    if (lane == 31) wtot[wid] = inc;
    __syncthreads();
    if (wid == 0) {
        int v = wtot[lane];
        int s = v;
#pragma unroll
        for (int off = 1; off < 32; off <<= 1) {
            int u = __shfl_up_sync(0xffffffffu, s, off);
            if (lane >= off) s += u;
        }
        wtot[lane] = s - v;
    }
    __syncthreads();
    int excl = wtot[wid] + inc - own;
#pragma unroll
    for (int t = 0; t < 5; ++t) {
        int idx = base + t;
        if (idx < NN) {
            g_rowptr[idx] = excl + loc[t];
            g_cursor[idx] = excl + loc[t];
        }
    }
    if (tid == 1023) g_rowptr[NN] = excl + own;
}

// ---------------- fill CSR slots ----------------
__global__ void k_fill(const int* __restrict__ dst) {
    int e = blockIdx.x * blockDim.x + threadIdx.x;
    if (e < EE) {
        int idx = atomicAdd(&g_cursor[dst[e]], 1);
        g_pos[e] = idx;
    }
}

// ---------------- per-edge tiny MLP -> CSR-ordered (c0,c1) + src ----------
__global__ void __launch_bounds__(256) k_cmlp(
    const float* __restrict__ dist,
    const float* __restrict__ w1, const float* __restrict__ b1,
    const float* __restrict__ w2, const float* __restrict__ b2,
    const int* __restrict__ src, const int* __restrict__ dst)
{
    __shared__ float w1s[96 * 16];
    __shared__ float b1s[16];
    __shared__ float w2s[32];
    __shared__ float b2s[2];
    int tid = threadIdx.x;
    for (int i = tid; i < 96 * 16; i += 256) w1s[i] = w1[i];
    if (tid < 16) b1s[tid] = b1[tid];
    if (tid < 32) w2s[tid] = w2[tid];
    if (tid < 2)  b2s[tid] = b2[tid];
    __syncthreads();

    int e = blockIdx.x * 256 + tid;
    if (e >= EE) return;
    int s = src[e], d = dst[e];

    float h1[16];
#pragma unroll
    for (int j = 0; j < 16; ++j) h1[j] = b1s[j];

    const float4* fs4 = reinterpret_cast<const float4*>(g_featp + s * FPAD);
    const float4* fd4 = reinterpret_cast<const float4*>(g_featp + d * FPAD);

#pragma unroll
    for (int q = 0; q < 12; ++q) {
        float4 f = fs4[q];
        int i0 = q * 4;
#pragma unroll
        for (int j = 0; j < 16; ++j) {
            h1[j] = fmaf(f.x, w1s[(i0 + 0) * 16 + j], h1[j]);
            h1[j] = fmaf(f.y, w1s[(i0 + 1) * 16 + j], h1[j]);
            h1[j] = fmaf(f.z, w1s[(i0 + 2) * 16 + j], h1[j]);
            h1[j] = fmaf(f.w, w1s[(i0 + 3) * 16 + j], h1[j]);
        }
    }
#pragma unroll
    for (int q = 0; q < 12; ++q) {
        float4 f = fd4[q];
        int i0 = 47 + q * 4;
#pragma unroll
        for (int j = 0; j < 16; ++j) {
            h1[j] = fmaf(f.x, w1s[(i0 + 0) * 16 + j], h1[j]);
            h1[j] = fmaf(f.y, w1s[(i0 + 1) * 16 + j], h1[j]);
            h1[j] = fmaf(f.z, w1s[(i0 + 2) * 16 + j], h1[j]);
            h1[j] = fmaf(f.w, w1s[(i0 + 3) * 16 + j], h1[j]);
        }
    }
    float d0 = dist[2 * e], d1 = dist[2 * e + 1];
#pragma unroll
    for (int j = 0; j < 16; ++j) {
        h1[j] = fmaf(d0, w1s[94 * 16 + j], h1[j]);
        h1[j] = fmaf(d1, w1s[95 * 16 + j], h1[j]);
        h1[j] = fsigmoid(h1[j]);
    }
    float c0 = b2s[0], c1 = b2s[1];
#pragma unroll
    for (int j = 0; j < 16; ++j) {
        c0 = fmaf(h1[j], w2s[2 * j],     c0);
        c1 = fmaf(h1[j], w2s[2 * j + 1], c1);
    }
    int p = g_pos[e];
    g_cp[p]   = make_float2(fsigmoid(c0), fsigmoid(c1));
    g_srcp[p] = s;
}

// ---------------- main gather kernel: edge-parallel warps ----------------
// CTA = 128 threads = 4 warps; warp w handles edges ei = rs+w, rs+w+4, ...
// lane = h. Each thread regenerates its W column W[:,h] into REGISTERS
// (wk[32] packed pairs) and runs the einsum for all 16 b. No Wt in smem,
// no __syncthreads in the main loop; one __syncwarp per edge. Final den/num
// reduced across the 4 warps once per node.
__global__ void __launch_bounds__(128) k_main(
    const float* __restrict__ state,
    const float* __restrict__ w3, const float* __restrict__ b3,
    const float* __restrict__ weight,
    float* __restrict__ out)
{
    const int n   = blockIdx.x;
    const int tid = threadIdx.x;
    const int h   = tid & 31;
    const int wid = tid >> 5;

    __shared__ __align__(16) ull   w3ps[3072];       // A | B | C packed k-pairs, [p*32+h]
    __shared__ __align__(16) float sbw[4][2][512];   // per-warp double-buffered state[src]
    __shared__ __align__(16) float sd[512];          // state[n] (dst half), shared

    // fill w3ps: w3ps[arr*1024 + p*32 + h] = pk(arr[2p*32+h], arr[(2p+1)*32+h])
    for (int idx = tid; idx < 3072; idx += 128) {
        int arr = idx >> 10, rem = idx & 1023, p = rem >> 5, hh = rem & 31;
        const float* sp = (arr == 0) ? w3 : (arr == 1) ? (w3 + 2048) : b3;
        w3ps[idx] = pk(sp[(2 * p) * 32 + hh], sp[(2 * p + 1) * 32 + hh]);
    }
    {
        int j = tid * 4;
        *reinterpret_cast<float4*>(&sd[j]) =
            *reinterpret_cast<const float4*>(state + n * 512 + j);
    }
    __syncthreads();

    const uint32_t w3ps_b = (uint32_t)__cvta_generic_to_shared(w3ps);
    const uint32_t sd_b   = (uint32_t)__cvta_generic_to_shared(sd);
    const uint32_t sbw_b  = (uint32_t)__cvta_generic_to_shared(&sbw[wid][0][0]);

    const int rs = g_rowptr[n], re = g_rowptr[n + 1];

    float den[16], num[16];
#pragma unroll
    for (int b = 0; b < 16; ++b) { den[b] = 0.f; num[b] = 0.f; }

    int ei = rs + wid;
    if (ei < re) {
        float2 cc = g_cp[ei];
        int    sn = g_srcp[ei];
        {   // stage first edge's state[src] into buf 0 (register-free)
            const float* src = state + sn * 512;
#pragma unroll
            for (int i = 0; i < 4; ++i)
                cpasync16(sbw_b + (uint32_t)(i * 128 + h * 4) * 4u, src + i * 128 + h * 4);
            CP_COMMIT();
        }
        int buf = 0;
        while (ei < re) {
            CP_WAIT0();          // this lane's copies for current buf done
            __syncwarp();        // all lanes' copies visible

            // prefetch next edge (cp.async into other buffer)
            int ni = ei + 4;
            int pi = (ni < re) ? ni : ei;
            float2 ccn = g_cp[pi];
            int    snn = g_srcp[pi];
            if (ni < re) {
                const float* src = state + snn * 512;
                uint32_t db = sbw_b + (uint32_t)(buf ^ 1) * 2048u;
#pragma unroll
                for (int i = 0; i < 4; ++i)
                    cpasync16(db + (uint32_t)(i * 128 + h * 4) * 4u, src + i * 128 + h * 4);
            }
            CP_COMMIT();

            // ---- regen W column h into registers ----
            ull wk[32];
            {
                ull c0d = pk(cc.x, cc.x), c1d = pk(cc.y, cc.y);
#pragma unroll
                for (int p = 0; p < 32; ++p) {
                    ull A, B, C;
                    lds1(A, w3ps_b + (uint32_t)(p * 32 + h) * 8u);
                    lds1(B, w3ps_b + (uint32_t)(1024 + p * 32 + h) * 8u);
                    lds1(C, w3ps_b + (uint32_t)(2048 + p * 32 + h) * 8u);
                    ull x = C;
                    ffma2(x, c1d, B);
                    ffma2(x, c0d, A);
                    float xl, xh; upk(xl, xh, x);
                    wk[p] = pk(fsigmoid(xl), fsigmoid(xh));
                }
            }

            // ---- einsum for all 16 b + softmax accumulation ----
            uint32_t sb_cur = sbw_b + (uint32_t)buf * 2048u;
#pragma unroll
            for (int b = 0; b < 16; ++b) {
                uint32_t srow = sb_cur + (uint32_t)b * 128u;
                uint32_t drow = sd_b   + (uint32_t)b * 128u;
                ull a0 = 0ull, a1 = 0ull;
#pragma unroll
                for (int kc = 0; kc < 8; ++kc) {          // src half: k = 0..31
                    ull s0, s1; lds2(s0, s1, srow + kc * 16);
                    ffma2(a0, s0, wk[2 * kc]);
                    ffma2(a1, s1, wk[2 * kc + 1]);
                }
#pragma unroll
                for (int kc = 0; kc < 8; ++kc) {          // dst half: k = 32..63
                    ull s0, s1; lds2(s0, s1, drow + kc * 16);
                    ffma2(a0, s0, wk[16 + 2 * kc]);
                    ffma2(a1, s1, wk[17 + 2 * kc]);
                }
                float l0, h0, l1, h1_;
                upk(l0, h0, a0); upk(l1, h1_, a1);
                float a = (l0 + h0) + (l1 + h1_);
                a = fmaxf(a, 0.01f * a);                  // leaky_relu
                float ex = __expf(a);
                float sval;
                asm volatile("ld.shared.f32 %0, [%1];" : "=f"(sval) : "r"(srow + h * 4));
                den[b] += ex;
                num[b] = fmaf(ex, sval, num[b]);
            }

            __syncwarp();        // all lanes done reading buf before its next overwrite
            cc = ccn; sn = snn;
            ei = ni; buf ^= 1;
        }
    }

    __syncthreads();
    // cross-warp reduction of den/num (reuse w3ps storage)
    float* redd = reinterpret_cast<float*>(w3ps);   // [4][512]
    float* redn = redd + 2048;                      // [4][512]
#pragma unroll
    for (int b = 0; b < 16; ++b) {
        redd[wid * 512 + b * 32 + h] = den[b];
        redn[wid * 512 + b * 32 + h] = num[b];
    }
    __syncthreads();
    float sigw = __fdividef(1.0f, 1.0f + __expf(-weight[0]));
#pragma unroll
    for (int t = 0; t < 4; ++t) {
        int slot = tid + t * 128;
        float d = redd[slot] + redd[512 + slot] + redd[1024 + slot] + redd[1536 + slot];
        float m = redn[slot] + redn[512 + slot] + redn[1024 + slot] + redn[1536 + slot];
        d = (d > 0.f) ? d : 1.f;
        float v = __fdividef(m, d) * sigw;
        out[n * 512 + slot] = (v > 0.f) ? v : 0.f;
    }
}

// ---------------- launch ----------------
extern "C" void kernel_launch(void* const* d_in, const int* in_sizes, int n_in,
                              void* d_out, int out_size)
{
    const float* state   = (const float*)d_in[0];
    const float* feature = (const float*)d_in[1];
    const float* dist    = (const float*)d_in[2];
    const float* w1      = (const float*)d_in[3];
    const float* b1      = (const float*)d_in[4];
    const float* w2      = (const float*)d_in[5];
    const float* b2      = (const float*)d_in[6];
    const float* w3      = (const float*)d_in[7];
    const float* b3      = (const float*)d_in[8];
    const float* weight  = (const float*)d_in[9];
    const int*   src     = (const int*)d_in[10];
    const int*   dst     = (const int*)d_in[11];
    float* out = (float*)d_out;

    k_prep <<<(NN * FPAD + 255) / 256, 256>>>(feature);
    k_count<<<(EE + 255) / 256, 256>>>(dst);
    k_scan <<<1, 1024>>>();
    k_fill <<<(EE + 255) / 256, 256>>>(dst);
    k_cmlp <<<(EE + 255) / 256, 256>>>(dist, w1, b1, w2, b2, src, dst);
    k_main <<<NN, 128>>>(state, w3, b3, weight, out);
}

// round 7
// speedup vs baseline: 1.1457x; 1.1457x over previous
#include <cuda_runtime.h>
#include <cstdint>

#define NN   5000
#define EE   80000
#define FEAT 47
#define FPAD 48
#define WT_STRIDE 68

using ull = unsigned long long;

// ---------------- device scratch ----------------
__device__ int    g_count [NN];        // zero at load (BSS); re-zeroed by k_scan
__device__ int    g_rowptr[NN + 1];
__device__ int    g_cursor[NN];
__device__ int    g_srcp  [EE];        // CSR-ordered src node
__device__ float2 g_cp    [EE];        // CSR-ordered (c0, c1)
__device__ float  g_featp [NN * FPAD];

__device__ __forceinline__ float ftanh(float x) {
    float r; asm("tanh.approx.f32 %0, %1;" : "=f"(r) : "f"(x)); return r;
}
__device__ __forceinline__ float fsigmoid(float x) {     // 1 MUFU
    return fmaf(0.5f, ftanh(0.5f * x), 0.5f);
}
__device__ __forceinline__ ull pk(float lo, float hi) {
    ull r; asm("mov.b64 %0, {%1, %2};" : "=l"(r) : "f"(lo), "f"(hi)); return r;
}
__device__ __forceinline__ void upk(float& lo, float& hi, ull v) {
    asm("mov.b64 {%0, %1}, %2;" : "=f"(lo), "=f"(hi) : "l"(v));
}
__device__ __forceinline__ void ffma2(ull& acc, ull a, ull b) {
    asm("fma.rn.f32x2 %0, %1, %2, %0;" : "+l"(acc) : "l"(a), "l"(b));
}
__device__ __forceinline__ void lds2(ull& a, ull& b, uint32_t addr) {
    asm volatile("ld.shared.v2.b64 {%0, %1}, [%2];" : "=l"(a), "=l"(b) : "r"(addr));
}

// ---------------- kernel 0: pad features + count edges per dst ------------
// Independent arrays -> safe to fuse. g_count must be zero on entry: true at
// module load (BSS) and re-established by k_scan each call.
__global__ void k_pc(const float* __restrict__ feature, const int* __restrict__ dst) {
    int i = blockIdx.x * blockDim.x + threadIdx.x;
    if (i < NN * FPAD) {
        int n = i / FPAD, c = i % FPAD;
        g_featp[i] = (c < FEAT) ? feature[n * FEAT + c] : 0.0f;
    }
    if (i < EE) atomicAdd(&g_count[dst[i]], 1);
}

// ---------------- kernel 1: exclusive scan + re-zero counters -------------
__global__ void k_scan() {
    __shared__ int wtot[32];
    int tid = threadIdx.x, lane = tid & 31, wid = tid >> 5;
    int base = tid * 5;
    int loc[5];
    int run = 0;
#pragma unroll
    for (int t = 0; t < 5; ++t) {
        loc[t] = run;
        int idx = base + t;
        if (idx < NN) {
            run += g_count[idx];
            g_count[idx] = 0;          // ready for next kernel_launch call
        }
    }
    int own = run;
    int inc = run;
#pragma unroll
    for (int off = 1; off < 32; off <<= 1) {
        int v = __shfl_up_sync(0xffffffffu, inc, off);
        if (lane >= off) inc += v;
    }
    if (lane == 31) wtot[wid] = inc;
    __syncthreads();
    if (wid == 0) {
        int v = wtot[lane];
        int s = v;
#pragma unroll
        for (int off = 1; off < 32; off <<= 1) {
            int u = __shfl_up_sync(0xffffffffu, s, off);
            if (lane >= off) s += u;
        }
        wtot[lane] = s - v;
    }
    __syncthreads();
    int excl = wtot[wid] + inc - own;
#pragma unroll
    for (int t = 0; t < 5; ++t) {
        int idx = base + t;
        if (idx < NN) {
            g_rowptr[idx] = excl + loc[t];
            g_cursor[idx] = excl + loc[t];
        }
    }
    if (tid == 1023) g_rowptr[NN] = excl + own;
}

// ---------------- kernel 2: per-edge MLP + CSR fill (fused) ---------------
__global__ void __launch_bounds__(256) k_cmlp(
    const float* __restrict__ dist,
    const float* __restrict__ w1, const float* __restrict__ b1,
    const float* __restrict__ w2, const float* __restrict__ b2,
    const int* __restrict__ src, const int* __restrict__ dst)
{
    __shared__ float w1s[96 * 16];
    __shared__ float b1s[16];
    __shared__ float w2s[32];
    __shared__ float b2s[2];
    int tid = threadIdx.x;
    for (int i = tid; i < 96 * 16; i += 256) w1s[i] = w1[i];
    if (tid < 16) b1s[tid] = b1[tid];
    if (tid < 32) w2s[tid] = w2[tid];
    if (tid < 2)  b2s[tid] = b2[tid];
    __syncthreads();

    int e = blockIdx.x * 256 + tid;
    if (e >= EE) return;
    int s = src[e], d = dst[e];

    float h1[16];
#pragma unroll
    for (int j = 0; j < 16; ++j) h1[j] = b1s[j];

    const float4* fs4 = reinterpret_cast<const float4*>(g_featp + s * FPAD);
    const float4* fd4 = reinterpret_cast<const float4*>(g_featp + d * FPAD);

#pragma unroll
    for (int q = 0; q < 12; ++q) {
        float4 f = fs4[q];
        int i0 = q * 4;
#pragma unroll
        for (int j = 0; j < 16; ++j) {
            h1[j] = fmaf(f.x, w1s[(i0 + 0) * 16 + j], h1[j]);
            h1[j] = fmaf(f.y, w1s[(i0 + 1) * 16 + j], h1[j]);
            h1[j] = fmaf(f.z, w1s[(i0 + 2) * 16 + j], h1[j]);
            h1[j] = fmaf(f.w, w1s[(i0 + 3) * 16 + j], h1[j]);
        }
    }
#pragma unroll
    for (int q = 0; q < 12; ++q) {
        float4 f = fd4[q];
        int i0 = 47 + q * 4;
#pragma unroll
        for (int j = 0; j < 16; ++j) {
            h1[j] = fmaf(f.x, w1s[(i0 + 0) * 16 + j], h1[j]);
            h1[j] = fmaf(f.y, w1s[(i0 + 1) * 16 + j], h1[j]);
            h1[j] = fmaf(f.z, w1s[(i0 + 2) * 16 + j], h1[j]);
            h1[j] = fmaf(f.w, w1s[(i0 + 3) * 16 + j], h1[j]);
        }
    }
    float d0 = dist[2 * e], d1 = dist[2 * e + 1];
#pragma unroll
    for (int j = 0; j < 16; ++j) {
        h1[j] = fmaf(d0, w1s[94 * 16 + j], h1[j]);
        h1[j] = fmaf(d1, w1s[95 * 16 + j], h1[j]);
        h1[j] = fsigmoid(h1[j]);
    }
    float c0 = b2s[0], c1 = b2s[1];
#pragma unroll
    for (int j = 0; j < 16; ++j) {
        c0 = fmaf(h1[j], w2s[2 * j],     c0);
        c1 = fmaf(h1[j], w2s[2 * j + 1], c1);
    }
    int p = atomicAdd(&g_cursor[d], 1);   // CSR slot (fused k_fill)
    g_cp[p]   = make_float2(fsigmoid(c0), fsigmoid(c1));
    g_srcp[p] = s;
}

// ---------------- kernel 3: main gather kernel (R4 champion design) -------
// 1 CTA per dst node, 128 threads; thread = (bq = tid>>5, h = tid&31);
// owns outputs (b,h), b = bq*4+i. w3/b3 slices in registers; Wt/sb
// double-buffered; edge i+1's (c,src,state) prefetched into registers
// before edge i's barrier. One __syncthreads per edge.
__global__ void __launch_bounds__(128) k_main(
    const float* __restrict__ state,
    const float* __restrict__ w3, const float* __restrict__ b3,
    const float* __restrict__ weight,
    float* __restrict__ out)
{
    const int n   = blockIdx.x;
    const int tid = threadIdx.x;
    const int h   = tid & 31;
    const int bq  = tid >> 5;

    __shared__ __align__(16) float Wt[2][32 * WT_STRIDE];
    __shared__ __align__(16) float sb[2][16 * 64];

    // w3/b3 slices into registers (packed over k-pairs)
    ull rap[8], rbp[8], rcp[8];
#pragma unroll
    for (int p = 0; p < 8; ++p) {
        int j0 = (bq * 16 + 2 * p) * 32 + h;
        int j1 = j0 + 32;
        rap[p] = pk(w3[j0],        w3[j1]);
        rbp[p] = pk(w3[2048 + j0], w3[2048 + j1]);
        rcp[p] = pk(b3[j0],        b3[j1]);
    }
    // state[n] (dst half) into both buffers, k = 32..63
    const int idx = tid * 4, bb = idx >> 5, hh = idx & 31;
    {
        float4 v = *reinterpret_cast<const float4*>(state + n * 512 + idx);
        *reinterpret_cast<float4*>(&sb[0][bb * 64 + 32 + hh]) = v;
        *reinterpret_cast<float4*>(&sb[1][bb * 64 + 32 + hh]) = v;
    }

    const int rs = g_rowptr[n];
    const int re = g_rowptr[n + 1];

    uint32_t sb_base = (uint32_t)__cvta_generic_to_shared(&sb[0][0]);
    uint32_t wt_base = (uint32_t)__cvta_generic_to_shared(&Wt[0][0]);

    float den[4] = {0.f, 0.f, 0.f, 0.f};
    float num[4] = {0.f, 0.f, 0.f, 0.f};

    if (rs < re) {
        float2 cc = g_cp[rs];
        int    sn = g_srcp[rs];
        float4 sv = *reinterpret_cast<const float4*>(state + sn * 512 + idx);

        for (int ei = rs; ei < re; ++ei) {
            const int buf = (ei - rs) & 1;

            int ni = (ei + 1 < re) ? (ei + 1) : ei;
            float2 ccn = g_cp[ni];
            int    snn = g_srcp[ni];

            *reinterpret_cast<float4*>(&sb[buf][bb * 64 + hh]) = sv;

            {
                ull c0d = pk(cc.x, cc.x), c1d = pk(cc.y, cc.y);
                float wtmp[16];
#pragma unroll
                for (int p = 0; p < 8; ++p) {
                    ull x = rcp[p];
                    ffma2(x, c1d, rbp[p]);
                    ffma2(x, c0d, rap[p]);
                    float xl, xh; upk(xl, xh, x);
                    wtmp[2 * p]     = fsigmoid(xl);
                    wtmp[2 * p + 1] = fsigmoid(xh);
                }
#pragma unroll
                for (int q = 0; q < 4; ++q)
                    *reinterpret_cast<float4*>(&Wt[buf][h * WT_STRIDE + bq * 16 + q * 4]) =
                        make_float4(wtmp[4 * q], wtmp[4 * q + 1], wtmp[4 * q + 2], wtmp[4 * q + 3]);
            }

            float4 svn = *reinterpret_cast<const float4*>(state + snn * 512 + idx);

            __syncthreads();

            uint32_t wrow = wt_base + (uint32_t)(buf * 32 * WT_STRIDE + h * WT_STRIDE) * 4u;
            uint32_t srow = sb_base + (uint32_t)(buf * 16 * 64 + (bq * 4) * 64) * 4u;
            ull accp[4] = {0ull, 0ull, 0ull, 0ull};
#pragma unroll
            for (int kc = 0; kc < 16; ++kc) {
                ull w0, w1; lds2(w0, w1, wrow + kc * 16);
#pragma unroll
                for (int i = 0; i < 4; ++i) {
                    ull s0, s1; lds2(s0, s1, srow + i * 256 + kc * 16);
                    ffma2(accp[i], s0, w0);
                    ffma2(accp[i], s1, w1);
                }
            }
#pragma unroll
            for (int i = 0; i < 4; ++i) {
                float lo, hi; upk(lo, hi, accp[i]);
                float a = lo + hi;
                a = fmaxf(a, 0.01f * a);           // leaky_relu
                float ex = __expf(a);
                den[i] += ex;
                float sval = sb[buf][(bq * 4 + i) * 64 + h];
                num[i] = fmaf(ex, sval, num[i]);
            }

            cc = ccn; sn = snn; sv = svn;
        }
    }

    float sigw = __fdividef(1.0f, 1.0f + __expf(-weight[0]));
#pragma unroll
    for (int i = 0; i < 4; ++i) {
        float d = (den[i] > 0.f) ? den[i] : 1.f;
        float v = __fdividef(num[i], d) * sigw;
        out[n * 512 + (bq * 4 + i) * 32 + h] = (v > 0.f) ? v : 0.f;
    }
}

// ---------------- launch: 4 kernels, k_main at index 3 (ncu captures it) ---
extern "C" void kernel_launch(void* const* d_in, const int* in_sizes, int n_in,
                              void* d_out, int out_size)
{
    const float* state   = (const float*)d_in[0];
    const float* feature = (const float*)d_in[1];
    const float* dist    = (const float*)d_in[2];
    const float* w1      = (const float*)d_in[3];
    const float* b1      = (const float*)d_in[4];
    const float* w2      = (const float*)d_in[5];
    const float* b2      = (const float*)d_in[6];
    const float* w3      = (const float*)d_in[7];
    const float* b3      = (const float*)d_in[8];
    const float* weight  = (const float*)d_in[9];
    const int*   src     = (const int*)d_in[10];
    const int*   dst     = (const int*)d_in[11];
    float* out = (float*)d_out;

    k_pc   <<<(NN * FPAD + 255) / 256, 256>>>(feature, dst);
    k_scan <<<1, 1024>>>();
    k_cmlp <<<(EE + 255) / 256, 256>>>(dist, w1, b1, w2, b2, src, dst);
    k_main <<<NN, 128>>>(state, w3, b3, weight, out);
}